// round 1
// baseline (speedup 1.0000x reference)
#include <cuda_runtime.h>
#include <math.h>

#define BB   8
#define CC   3
#define NN   4096
#define KK   20
#define HH   64
#define DOUT 64

// scratch for KNN indices (allocation-free rule: __device__ global)
__device__ int g_idx[BB * NN * KK];

// ---------------------------------------------------------------------------
// Kernel 1: brute-force KNN with top-20 selection.
// One block handles 128 points of one batch; full batch point cloud in SMEM.
// Ranking key: d' = 2*inner(n,m) - xx[m]  (== dist + xx[n], order-equivalent)
// ---------------------------------------------------------------------------
__global__ void __launch_bounds__(128) knn_kernel(const float* __restrict__ x) {
    __shared__ float sx0[NN];
    __shared__ float sx1[NN];
    __shared__ float sx2[NN];

    const int b = blockIdx.y;
    const float* xb = x + (size_t)b * CC * NN;

    for (int i = threadIdx.x; i < NN; i += blockDim.x) {
        sx0[i] = xb[i];
        sx1[i] = xb[NN + i];
        sx2[i] = xb[2 * NN + i];
    }
    __syncthreads();

    const int n = blockIdx.x * blockDim.x + threadIdx.x;
    const float a0 = 2.0f * sx0[n];
    const float a1 = 2.0f * sx1[n];
    const float a2 = 2.0f * sx2[n];

    float vals[KK];
    int   idxs[KK];
#pragma unroll
    for (int i = 0; i < KK; i++) { vals[i] = -INFINITY; idxs[i] = 0; }
    float vmin = -INFINITY;
    int   mslot = 0;

#pragma unroll 4
    for (int m = 0; m < NN; m++) {
        const float x0 = sx0[m], x1 = sx1[m], x2 = sx2[m];
        // xxm = x0^2+x1^2+x2^2 ; d = a0*x0+a1*x1+a2*x2 - xxm
        float d = (a0 - x0) * x0;
        d = fmaf(a1 - x1, x1, d);
        d = fmaf(a2 - x2, x2, d);
        if (d > vmin) {
            // replace current min slot (unrolled so arrays stay in registers)
#pragma unroll
            for (int i = 0; i < KK; i++)
                if (i == mslot) { vals[i] = d; idxs[i] = m; }
            // recompute min
            vmin = vals[0]; mslot = 0;
#pragma unroll
            for (int i = 1; i < KK; i++)
                if (vals[i] < vmin) { vmin = vals[i]; mslot = i; }
        }
    }

    int* op = g_idx + ((size_t)b * NN + n) * KK;
#pragma unroll
    for (int i = 0; i < KK; i++) op[i] = idxs[i];
}

// ---------------------------------------------------------------------------
// Kernel 2: fused edge-feature conv + BN + ReLU + max/mean pool + conv_out.
// One block (64 threads) per point; thread t = output channel.
// ---------------------------------------------------------------------------
__global__ void __launch_bounds__(64) edge_kernel(
    const float* __restrict__ x,
    const float* __restrict__ w1,  const float* __restrict__ b1,
    const float* __restrict__ g1,  const float* __restrict__ beta1,
    const float* __restrict__ rm1, const float* __restrict__ rv1,
    const float* __restrict__ w2,  const float* __restrict__ b2,
    const float* __restrict__ g2,  const float* __restrict__ beta2,
    const float* __restrict__ rm2, const float* __restrict__ rv2,
    float* __restrict__ out, float* __restrict__ m1o, float* __restrict__ m2o)
{
    const int t = threadIdx.x;          // output channel 0..63
    const int p = blockIdx.x;           // b*N + n
    const int b = p >> 12;              // N = 4096
    const int n = p & (NN - 1);

    __shared__ float s_nb[KK][3];
    __shared__ float s_cat[2 * HH];

    const float* xb = x + (size_t)b * CC * NN;
    const float c0 = __ldg(xb + n);
    const float c1 = __ldg(xb + NN + n);
    const float c2 = __ldg(xb + 2 * NN + n);

    const int* ip = g_idx + (size_t)p * KK;
    for (int j = t; j < KK * 3; j += 64) {
        const int k = j / 3, c = j % 3;
        const int m = __ldg(ip + k);
        s_nb[k][c] = __ldg(xb + c * NN + m);
    }
    __syncthreads();

    // layer-1 weights + folded BN params for this channel
    const float W0 = __ldg(w1 + t * 6 + 0);
    const float W1 = __ldg(w1 + t * 6 + 1);
    const float W2 = __ldg(w1 + t * 6 + 2);
    const float W3 = __ldg(w1 + t * 6 + 3);
    const float W4 = __ldg(w1 + t * 6 + 4);
    const float W5 = __ldg(w1 + t * 6 + 5);
    const float sc1 = __ldg(g1 + t) * rsqrtf(__ldg(rv1 + t) + 1e-5f);
    const float bi1 = (__ldg(b1 + t) - __ldg(rm1 + t)) * sc1 + __ldg(beta1 + t);
    const float cdot = c0 * W3 + c1 * W4 + c2 * W5;   // center part, k-invariant

    float mx = -INFINITY, sm = 0.0f;
#pragma unroll
    for (int k = 0; k < KK; k++) {
        const float e0 = s_nb[k][0] - c0;
        const float e1 = s_nb[k][1] - c1;
        const float e2 = s_nb[k][2] - c2;
        float dot = cdot;
        dot = fmaf(e0, W0, dot);
        dot = fmaf(e1, W1, dot);
        dot = fmaf(e2, W2, dot);
        const float h = fmaxf(fmaf(dot, sc1, bi1), 0.0f);
        mx = fmaxf(mx, h);
        sm += h;
    }
    const float mean = sm * (1.0f / KK);

    s_cat[t] = mx;
    s_cat[HH + t] = mean;

    const size_t obase = ((size_t)b * HH + t) * NN + n;
    m1o[obase] = mx;
    m2o[obase] = mean;
    __syncthreads();

    // layer 2: 128-wide dot from SMEM, W2 row via float4
    const float sc2 = __ldg(g2 + t) * rsqrtf(__ldg(rv2 + t) + 1e-5f);
    const float bi2 = (__ldg(b2 + t) - __ldg(rm2 + t)) * sc2 + __ldg(beta2 + t);

    const float4* wrow = reinterpret_cast<const float4*>(w2 + (size_t)t * 2 * HH);
    float acc = 0.0f;
#pragma unroll
    for (int c = 0; c < (2 * HH) / 4; c++) {
        const float4 w = __ldg(wrow + c);
        acc = fmaf(w.x, s_cat[4 * c + 0], acc);
        acc = fmaf(w.y, s_cat[4 * c + 1], acc);
        acc = fmaf(w.z, s_cat[4 * c + 2], acc);
        acc = fmaf(w.w, s_cat[4 * c + 3], acc);
    }
    out[obase] = fmaxf(fmaf(acc, sc2, bi2), 0.0f);
}

// ---------------------------------------------------------------------------
extern "C" void kernel_launch(void* const* d_in, const int* in_sizes, int n_in,
                              void* d_out, int out_size) {
    const float* x     = (const float*)d_in[0];
    const float* w1    = (const float*)d_in[1];
    const float* b1    = (const float*)d_in[2];
    const float* g1    = (const float*)d_in[3];
    const float* beta1 = (const float*)d_in[4];
    const float* rm1   = (const float*)d_in[5];
    const float* rv1   = (const float*)d_in[6];
    const float* w2    = (const float*)d_in[7];
    const float* b2    = (const float*)d_in[8];
    const float* g2    = (const float*)d_in[9];
    const float* beta2 = (const float*)d_in[10];
    const float* rm2   = (const float*)d_in[11];
    const float* rv2   = (const float*)d_in[12];

    float* out = (float*)d_out;
    float* m1o = out + (size_t)BB * HH * NN;
    float* m2o = m1o + (size_t)BB * HH * NN;

    knn_kernel<<<dim3(NN / 128, BB), 128>>>(x);
    edge_kernel<<<BB * NN, 64>>>(x, w1, b1, g1, beta1, rm1, rv1,
                                 w2, b2, g2, beta2, rm2, rv2,
                                 out, m1o, m2o);
}

// round 2
// speedup vs baseline: 3.0202x; 3.0202x over previous
#include <cuda_runtime.h>
#include <math.h>

#define BB   8
#define CC   3
#define NN   4096
#define KK   20
#define HH   64
#define DOUT 64

// scratch for KNN indices (allocation-free rule: __device__ global)
__device__ int g_idx[BB * NN * KK];

// ---------------------------------------------------------------------------
// Kernel 1: brute-force KNN, buffered top-20 selection.
// Per-iteration: predicated push into a local-memory buffer vs a (stale)
// threshold -> no warp divergence in the hot loop. Warp-synchronous flush
// (ballot) merges buffers into the register top-20 list ~10x per thread.
// Ranking key: d' = 2*inner(n,m) - xx[m]  (== dist + xx[n], order-equivalent)
// ---------------------------------------------------------------------------
__global__ void __launch_bounds__(128) knn_kernel(const float* __restrict__ x) {
    __shared__ float sx0[NN];
    __shared__ float sx1[NN];
    __shared__ float sx2[NN];

    const int b = blockIdx.y;
    const float* xb = x + (size_t)b * CC * NN;

    for (int i = threadIdx.x; i < NN; i += blockDim.x) {
        sx0[i] = xb[i];
        sx1[i] = xb[NN + i];
        sx2[i] = xb[2 * NN + i];
    }
    __syncthreads();

    const int n = blockIdx.x * blockDim.x + threadIdx.x;
    const float a0 = 2.0f * sx0[n];
    const float a1 = 2.0f * sx1[n];
    const float a2 = 2.0f * sx2[n];

    float vals[KK];
    int   idxs[KK];
#pragma unroll
    for (int i = 0; i < KK; i++) { vals[i] = -INFINITY; idxs[i] = 0; }
    float vmin = -INFINITY;
    int   mslot = 0;

    // candidate buffer (local memory: indexable, cheap predicated stores)
    float bufd[32];
    int   bufm[32];
    int   cnt = 0;

    for (int m0 = 0; m0 < NN; m0 += 4) {
        float d[4];
#pragma unroll
        for (int u = 0; u < 4; u++) {
            const float x0 = sx0[m0 + u];
            const float x1 = sx1[m0 + u];
            const float x2 = sx2[m0 + u];
            float dd = (a0 - x0) * x0;
            dd = fmaf(a1 - x1, x1, dd);
            dd = fmaf(a2 - x2, x2, dd);
            d[u] = dd;
        }
#pragma unroll
        for (int u = 0; u < 4; u++) {
            if (d[u] > vmin) { bufd[cnt] = d[u]; bufm[cnt] = m0 + u; cnt++; }
        }
        // flush when any lane's buffer is nearly full (max growth 4/vote)
        if (__any_sync(0xffffffffu, cnt >= 24)) {
            for (int j = 0; j < cnt; j++) {
                const float dd = bufd[j];
                const int   mm = bufm[j];
                if (dd > vmin) {
#pragma unroll
                    for (int i = 0; i < KK; i++)
                        if (i == mslot) { vals[i] = dd; idxs[i] = mm; }
                    vmin = vals[0]; mslot = 0;
#pragma unroll
                    for (int i = 1; i < KK; i++)
                        if (vals[i] < vmin) { vmin = vals[i]; mslot = i; }
                }
            }
            cnt = 0;
        }
    }
    // final flush
    for (int j = 0; j < cnt; j++) {
        const float dd = bufd[j];
        const int   mm = bufm[j];
        if (dd > vmin) {
#pragma unroll
            for (int i = 0; i < KK; i++)
                if (i == mslot) { vals[i] = dd; idxs[i] = mm; }
            vmin = vals[0]; mslot = 0;
#pragma unroll
            for (int i = 1; i < KK; i++)
                if (vals[i] < vmin) { vmin = vals[i]; mslot = i; }
        }
    }

    int* op = g_idx + ((size_t)b * NN + n) * KK;
#pragma unroll
    for (int i = 0; i < KK; i++) op[i] = idxs[i];
}

// ---------------------------------------------------------------------------
// Kernel 2a: layer-1 (edge conv + BN + ReLU) + dual pooling.
// Thread = point, channel = loop -> coalesced m1/m2 stores, edge diffs in regs.
// ---------------------------------------------------------------------------
__global__ void __launch_bounds__(128) edgeA_kernel(
    const float* __restrict__ x,
    const float* __restrict__ w1,  const float* __restrict__ b1,
    const float* __restrict__ g1,  const float* __restrict__ beta1,
    const float* __restrict__ rm1, const float* __restrict__ rv1,
    float* __restrict__ m1o, float* __restrict__ m2o)
{
    __shared__ float sp[HH][8];   // W'*6, bias', pad

    const int tid = threadIdx.x;
    const int b = blockIdx.y;
    const int n = blockIdx.x * 128 + tid;

    if (tid < HH) {
        const float sc = __ldg(g1 + tid) * rsqrtf(__ldg(rv1 + tid) + 1e-5f);
#pragma unroll
        for (int c = 0; c < 6; c++) sp[tid][c] = __ldg(w1 + tid * 6 + c) * sc;
        sp[tid][6] = (__ldg(b1 + tid) - __ldg(rm1 + tid)) * sc + __ldg(beta1 + tid);
    }
    __syncthreads();

    const float* xb = x + (size_t)b * CC * NN;
    const float c0 = xb[n];
    const float c1 = xb[NN + n];
    const float c2 = xb[2 * NN + n];

    const int* ip = g_idx + ((size_t)b * NN + n) * KK;
    float e0[KK], e1[KK], e2[KK];
#pragma unroll
    for (int k = 0; k < KK; k++) {
        const int m = __ldg(ip + k);
        e0[k] = __ldg(xb + m) - c0;
        e1[k] = __ldg(xb + NN + m) - c1;
        e2[k] = __ldg(xb + 2 * NN + m) - c2;
    }

    const size_t ob = (size_t)b * HH * NN + n;
#pragma unroll 2
    for (int h = 0; h < HH; h++) {
        const float W0 = sp[h][0], W1 = sp[h][1], W2 = sp[h][2];
        const float W3 = sp[h][3], W4 = sp[h][4], W5 = sp[h][5];
        float cd = sp[h][6];
        cd = fmaf(c0, W3, cd);
        cd = fmaf(c1, W4, cd);
        cd = fmaf(c2, W5, cd);

        float mx = -INFINITY, sm = 0.0f;
#pragma unroll
        for (int k = 0; k < KK; k++) {
            float dt = cd;
            dt = fmaf(e0[k], W0, dt);
            dt = fmaf(e1[k], W1, dt);
            dt = fmaf(e2[k], W2, dt);
            dt = fmaxf(dt, 0.0f);
            mx = fmaxf(mx, dt);
            sm += dt;
        }
        m1o[ob + (size_t)h * NN] = mx;
        m2o[ob + (size_t)h * NN] = sm * (1.0f / KK);
    }
}

// ---------------------------------------------------------------------------
// Kernel 2b: layer-2 GEMM: out[b,o,n] = ReLU(BN(sum_c w2[o,c]*cat[b,c,n]))
// Block: 64 n-columns x all 64 outputs. w2 staged in SMEM (pad 129, no
// conflicts), activations read as broadcast float4, coalesced float4 stores.
// ---------------------------------------------------------------------------
__global__ void __launch_bounds__(256) edgeB_kernel(
    const float* __restrict__ m1o, const float* __restrict__ m2o,
    const float* __restrict__ w2,  const float* __restrict__ b2,
    const float* __restrict__ g2,  const float* __restrict__ beta2,
    const float* __restrict__ rm2, const float* __restrict__ rv2,
    float* __restrict__ out)
{
    __shared__ float sw[DOUT * 129];   // [o][c] padded rows
    __shared__ float ssc[DOUT], sbi[DOUT];

    const int tid = threadIdx.x;
    for (int i = tid; i < DOUT * 2 * HH; i += 256) {
        const int o = i >> 7, c = i & 127;
        sw[o * 129 + c] = __ldg(w2 + i);
    }
    if (tid < DOUT) {
        const float sc = __ldg(g2 + tid) * rsqrtf(__ldg(rv2 + tid) + 1e-5f);
        ssc[tid] = sc;
        sbi[tid] = (__ldg(b2 + tid) - __ldg(rm2 + tid)) * sc + __ldg(beta2 + tid);
    }
    __syncthreads();

    const int n4    = tid & 15;        // 16 float4 groups -> 64 n per block
    const int obase = tid >> 4;        // 0..15, thread covers o = obase+16j
    const int b  = blockIdx.y;
    const int n0 = blockIdx.x * 64 + n4 * 4;

    float4 acc[4];
#pragma unroll
    for (int j = 0; j < 4; j++) acc[j] = make_float4(0.f, 0.f, 0.f, 0.f);

    const float* cat0 = m1o + (size_t)b * HH * NN + n0;
    const float* cat1 = m2o + (size_t)b * HH * NN + n0;

#pragma unroll 2
    for (int c = 0; c < HH; c++) {
        const float4 v = __ldg(reinterpret_cast<const float4*>(cat0 + (size_t)c * NN));
#pragma unroll
        for (int j = 0; j < 4; j++) {
            const float w = sw[(obase + 16 * j) * 129 + c];
            acc[j].x = fmaf(w, v.x, acc[j].x);
            acc[j].y = fmaf(w, v.y, acc[j].y);
            acc[j].z = fmaf(w, v.z, acc[j].z);
            acc[j].w = fmaf(w, v.w, acc[j].w);
        }
    }
#pragma unroll 2
    for (int c = 0; c < HH; c++) {
        const float4 v = __ldg(reinterpret_cast<const float4*>(cat1 + (size_t)c * NN));
#pragma unroll
        for (int j = 0; j < 4; j++) {
            const float w = sw[(obase + 16 * j) * 129 + HH + c];
            acc[j].x = fmaf(w, v.x, acc[j].x);
            acc[j].y = fmaf(w, v.y, acc[j].y);
            acc[j].z = fmaf(w, v.z, acc[j].z);
            acc[j].w = fmaf(w, v.w, acc[j].w);
        }
    }

#pragma unroll
    for (int j = 0; j < 4; j++) {
        const int o = obase + 16 * j;
        const float sc = ssc[o], bi = sbi[o];
        float4 r;
        r.x = fmaxf(fmaf(acc[j].x, sc, bi), 0.0f);
        r.y = fmaxf(fmaf(acc[j].y, sc, bi), 0.0f);
        r.z = fmaxf(fmaf(acc[j].z, sc, bi), 0.0f);
        r.w = fmaxf(fmaf(acc[j].w, sc, bi), 0.0f);
        *reinterpret_cast<float4*>(out + ((size_t)b * DOUT + o) * NN + n0) = r;
    }
}

// ---------------------------------------------------------------------------
extern "C" void kernel_launch(void* const* d_in, const int* in_sizes, int n_in,
                              void* d_out, int out_size) {
    const float* x     = (const float*)d_in[0];
    const float* w1    = (const float*)d_in[1];
    const float* b1    = (const float*)d_in[2];
    const float* g1    = (const float*)d_in[3];
    const float* beta1 = (const float*)d_in[4];
    const float* rm1   = (const float*)d_in[5];
    const float* rv1   = (const float*)d_in[6];
    const float* w2    = (const float*)d_in[7];
    const float* b2    = (const float*)d_in[8];
    const float* g2    = (const float*)d_in[9];
    const float* beta2 = (const float*)d_in[10];
    const float* rm2   = (const float*)d_in[11];
    const float* rv2   = (const float*)d_in[12];

    float* out = (float*)d_out;
    float* m1o = out + (size_t)BB * HH * NN;
    float* m2o = m1o + (size_t)BB * HH * NN;

    knn_kernel<<<dim3(NN / 128, BB), 128>>>(x);
    edgeA_kernel<<<dim3(NN / 128, BB), 128>>>(x, w1, b1, g1, beta1, rm1, rv1,
                                              m1o, m2o);
    edgeB_kernel<<<dim3(NN / 64, BB), 256>>>(m1o, m2o, w2, b2, g2, beta2,
                                             rm2, rv2, out);
}